// round 7
// baseline (speedup 1.0000x reference)
#include <cuda_runtime.h>
#include <cstdint>
#include <cstddef>

namespace {

constexpr int kB   = 4096;
constexpr int kN   = 64;
constexpr int kOBS = 192;
constexpr int kACT = 64;
constexpr int kIN  = 256;
constexpr int kD   = 128;
constexpr int kFO  = 64;

constexpr int kThreads = 512;  // 16 warps, all MMA-active in every stage

// strides ≡ 4 (mod 32): conflict-free scalar fragment loads (proven R3/R6)
constexpr int SA_LD = 260;
constexpr int E_LD  = 132;
constexpr int S_LD  = 68;
constexpr int WG_LD = 36;

// SMEM plan (floats):
//  W0  [256x36]=9216 @ 0        (staging buf 0; f2 weights at the end)
//  W1  [256x36]=9216 @ 9216     (staging buf 1; SC [64x68]=4352 aliases it
//                                during scores->softmax->x, when no staging runs)
//  SA  [64x260]=16640 @ 18432   (dead after e/eq; then T [64x132]=8448 @18432,
//                                VT [128x68]=8704 @26880, H [64x68] @18432)
//  E   [64x132]=8448 @ 35584    (e; after scores dead -> X (x output) reuses it)
//  EQ  [64x132]=8448 @ 44032
constexpr int OFF_W0 = 0;
constexpr int OFF_W1 = 9216;
constexpr int OFF_SC = 9216;    // alias W1
constexpr int OFF_SA = 18432;
constexpr int OFF_T  = 18432;   // alias SA
constexpr int OFF_VT = 26880;   // alias SA (T+VT = 17152 <= reserved 17152)
constexpr int OFF_H  = 18432;   // alias T (dead after scores)
constexpr int OFF_E  = 35584;
constexpr int OFF_EQ = 44032;
constexpr int SMEM_FLOATS = 52480;
constexpr int SMEM_BYTES  = SMEM_FLOATS * 4;  // 209920

__device__ float gMt[kD * kD];  // gMt[j][i] = sum_d Wq[d][i]*Wk[d][j]

__device__ __forceinline__ float f2tf(float x) {
  uint32_t u;
  asm("cvt.rna.tf32.f32 %0, %1;" : "=r"(u) : "f"(x));
  return __uint_as_float(u);
}

__device__ __forceinline__ void mma8(float (&d)[4], const uint32_t (&a)[4],
                                     const uint32_t (&b)[2]) {
  asm volatile(
      "mma.sync.aligned.m16n8k8.row.col.f32.tf32.tf32.f32 "
      "{%0,%1,%2,%3}, {%4,%5,%6,%7}, {%8,%9}, {%0,%1,%2,%3};\n"
      : "+f"(d[0]), "+f"(d[1]), "+f"(d[2]), "+f"(d[3])
      : "r"(a[0]), "r"(a[1]), "r"(a[2]), "r"(a[3]), "r"(b[0]), "r"(b[1]));
}

// C[64 rows][NT*8 cols per warp] += A[64][KC] * B[cols][KC]^T   (R6 verbatim)
template <int NT, int KC>
__device__ __forceinline__ void mma_block(const float* __restrict__ As, int lda,
                                          const float* __restrict__ Bs, int ldb,
                                          float (&d)[2][NT][4],
                                          int lane, int wm, int wn) {
  const float* Aw = As + (wm * 32) * lda;
  const float* Bw = Bs + (wn * NT * 8) * ldb;
  const int gr = lane >> 2, gc = lane & 3;
#pragma unroll
  for (int k0 = 0; k0 < KC; k0 += 8) {
    uint32_t a[2][4];
#pragma unroll
    for (int mt = 0; mt < 2; mt++) {
      const float* p = Aw + (mt * 16 + gr) * lda + k0 + gc;
      a[mt][0] = __float_as_uint(p[0]);
      a[mt][1] = __float_as_uint(p[8 * lda]);
      a[mt][2] = __float_as_uint(p[4]);
      a[mt][3] = __float_as_uint(p[8 * lda + 4]);
    }
#pragma unroll
    for (int nt = 0; nt < NT; nt++) {
      const float* p = Bw + (nt * 8 + gr) * ldb + k0 + gc;
      uint32_t bf[2] = {__float_as_uint(p[0]), __float_as_uint(p[4])};
      mma8(d[0][nt], a[0], bf);
      mma8(d[1][nt], a[1], bf);
    }
  }
}

template <int NT, class F>
__device__ __forceinline__ void for_each(float (&d)[2][NT][4], int lane,
                                         int wm, int wn, F f) {
  const int gr = lane >> 2, gc = (lane & 3) * 2;
#pragma unroll
  for (int mt = 0; mt < 2; mt++)
#pragma unroll
    for (int nt = 0; nt < NT; nt++)
#pragma unroll
      for (int i = 0; i < 4; i++) {
        int row = wm * 32 + mt * 16 + gr + ((i >> 1) << 3);
        int col = wn * NT * 8 + nt * 8 + gc + (i & 1);
        f(row, col, d[mt][nt][i]);
      }
}

template <int NT>
__device__ __forceinline__ void zero_acc(float (&d)[2][NT][4]) {
#pragma unroll
  for (int mt = 0; mt < 2; mt++)
#pragma unroll
    for (int nt = 0; nt < NT; nt++)
#pragma unroll
      for (int i = 0; i < 4; i++) d[mt][nt][i] = 0.f;
}

// ---- staging: 512 threads stage [ON x 32] chunk; rows o>=SPLIT read Whi.
template <int ON>
__device__ __forceinline__ void ldg_chunk(float (&r)[ON / 16],
                                          const float* __restrict__ Wlo,
                                          const float* __restrict__ Whi,
                                          int split, int Kfull, int k0,
                                          int tid) {
#pragma unroll
  for (int j = 0; j < ON / 16; j++) {
    int i = tid + j * kThreads;
    int o = i >> 5, k = i & 31;
    const float* p = (o < split) ? (Wlo + o * Kfull) : (Whi + (o - split) * Kfull);
    r[j] = __ldg(p + k0 + k);
  }
}
template <int ON>
__device__ __forceinline__ void sts_chunk(float* buf, const float (&r)[ON / 16],
                                          int tid) {
#pragma unroll
  for (int j = 0; j < ON / 16; j++) {
    int i = tid + j * kThreads;
    int o = i >> 5, k = i & 31;
    buf[o * WG_LD + k] = f2tf(r[j]);
  }
}

// True double-buffered staged matmul: ONE sync per chunk.
// Iter c: ldg(c+1) | mma(cur) | sts(c+1 -> nxt) | sync.
// Safe: mma reads cur while sts writes nxt (disjoint); buffer reuse is two
// iterations (two syncs) away.
template <int ON, int NCH, int NT>
__device__ __forceinline__ void staged_mm(const float* __restrict__ A, int lda,
                                          const float* __restrict__ Wlo,
                                          const float* __restrict__ Whi,
                                          int split, int Kfull, int kbase,
                                          float (&d)[2][NT][4],
                                          float* w0, float* w1, int tid,
                                          int lane, int wm, int wn) {
  float r[ON / 16];
  ldg_chunk<ON>(r, Wlo, Whi, split, Kfull, kbase, tid);
  sts_chunk<ON>(w0, r, tid);
  __syncthreads();
#pragma unroll
  for (int c = 0; c < NCH; c++) {
    float* cur = (c & 1) ? w1 : w0;
    float* nxt = (c & 1) ? w0 : w1;
    const bool more = (c + 1 < NCH);
    if (more) ldg_chunk<ON>(r, Wlo, Whi, split, Kfull, kbase + (c + 1) * 32, tid);
    mma_block<NT, 32>(A + c * 32, lda, cur, WG_LD, d, lane, wm, wn);
    if (more) sts_chunk<ON>(nxt, r, tid);
    __syncthreads();
  }
}

// ---- prologue: gMt[j][i] = sum_d Wq[d][i]*Wk[d][j]
__global__ void precompute_mt(const float* __restrict__ Wq,
                              const float* __restrict__ Wk) {
  __shared__ float wkj[kD];
  const int j = blockIdx.x;
  const int i = threadIdx.x;
  wkj[i] = Wk[i * kD + j];
  __syncthreads();
  float s = 0.f;
#pragma unroll 8
  for (int dd = 0; dd < kD; dd++) s += Wq[dd * kD + i] * wkj[dd];
  gMt[j * kD + i] = s;
}

__global__ __launch_bounds__(kThreads, 1)
void critic_kernel(const float* __restrict__ states,
                   const float* __restrict__ actions,
                   const float* __restrict__ W_embed,
                   const float* __restrict__ b_embed,
                   const float* __restrict__ W_v,
                   const float* __restrict__ W_embed_q,
                   const float* __restrict__ b_embed_q,
                   const float* __restrict__ W_f1,
                   const float* __restrict__ W_f2,
                   float* __restrict__ outV,
                   float* __restrict__ outW) {
  extern __shared__ float smem[];
  const int b = blockIdx.x;
  const int tid = threadIdx.x;
  const int lane = tid & 31;
  const int warp = tid >> 5;
  const int wm = warp >> 3;   // row half (0/1)
  const int wn = warp & 7;    // col slice (0..7)

  float* W0 = smem + OFF_W0;
  float* W1 = smem + OFF_W1;
  float* SC = smem + OFF_SC;
  float* SA = smem + OFF_SA;
  float* T  = smem + OFF_T;
  float* VT = smem + OFF_VT;
  float* H  = smem + OFF_H;
  float* E  = smem + OFF_E;   // e; later x
  float* EQ = smem + OFF_EQ;

  // ---- load sa (visibility covered by first staged_mm sync)
  {
    const float* st = states + (size_t)b * kN * kOBS;
    const float* ac = actions + (size_t)b * kN * kACT;
#pragma unroll 4
    for (int j = 0; j < 32; j++) {
      int i = tid + j * kThreads;
      int t = i >> 8, c = i & 255;
      float v = (c < kOBS) ? st[t * kOBS + c] : ac[t * kACT + (c - kOBS)];
      SA[t * SA_LD + c] = f2tf(v);
    }
  }

  float d4[2][4][4];
  float d2[2][2][4];
  float d1[2][1][4];

  // ======== merged e|eq: [64,256] = sa @ [We; Weq]^T, 16 warps ===========
  zero_acc(d4);
  staged_mm<256, 8, 4>(SA, SA_LD, W_embed, W_embed_q, 128, kIN, 0,
                       d4, W0, W1, tid, lane, wm, wn);
  for_each<4>(d4, lane, wm, wn, [&](int r, int c, float v) {
    if (c < 128) {
      v += __ldg(b_embed + c);
      v = v > 0.f ? v : 0.01f * v;
      E[r * E_LD + c] = f2tf(v);
    } else {
      v += __ldg(b_embed_q + (c - 128));
      v = v > 0.f ? v : 0.01f * v;
      EQ[r * E_LD + (c - 128)] = f2tf(v);
    }
  });
  __syncthreads();  // SA dead; E complete before t/v reads it

  // ======== merged t|v: [64,256] = e @ [Mt; Wv]^T ========================
  zero_acc(d4);
  staged_mm<256, 4, 4>(E, E_LD, gMt, W_v, 128, kD, 0,
                       d4, W0, W1, tid, lane, wm, wn);
  for_each<4>(d4, lane, wm, wn, [&](int r, int c, float v) {
    if (c < 128) {
      T[r * E_LD + c] = f2tf(v);
    } else {
      VT[(c - 128) * S_LD + r] = f2tf(v);  // transposed
    }
  });
  __syncthreads();  // T, VT visible

  // ======== scores = t @ e^T / sqrt(D) -> SC (aliases W1; staging idle) ==
  zero_acc(d1);
  mma_block<1, 128>(T, E_LD, E, E_LD, d1, lane, wm, wn);
  for_each<1>(d1, lane, wm, wn, [&](int r, int c, float v) {
    SC[r * S_LD + c] = v * 0.08838834764831845f;
  });
  __syncthreads();

  // ======== row softmax: gmem fp32 + tf32 back into SC ===================
  {
    const int r = tid >> 3;
    const int c0 = (tid & 7) * 8;
    float* wrow = SC + r * S_LD + c0;
    float s[8];
#pragma unroll
    for (int j = 0; j < 8; j++) s[j] = wrow[j];
    float mx = -3.0e38f;
#pragma unroll
    for (int j = 0; j < 8; j++) mx = fmaxf(mx, s[j]);
    mx = fmaxf(mx, __shfl_xor_sync(0xffffffffu, mx, 1));
    mx = fmaxf(mx, __shfl_xor_sync(0xffffffffu, mx, 2));
    mx = fmaxf(mx, __shfl_xor_sync(0xffffffffu, mx, 4));
    float sum = 0.f;
#pragma unroll
    for (int j = 0; j < 8; j++) {
      s[j] = __expf(s[j] - mx);
      sum += s[j];
    }
    sum += __shfl_xor_sync(0xffffffffu, sum, 1);
    sum += __shfl_xor_sync(0xffffffffu, sum, 2);
    sum += __shfl_xor_sync(0xffffffffu, sum, 4);
    float inv = 1.f / sum;
    float* og = outW + ((size_t)b * kN + r) * kN + c0;
#pragma unroll
    for (int j = 0; j < 8; j++) {
      float wv = s[j] * inv;
      og[j] = wv;
      wrow[j] = f2tf(wv);
    }
  }
  __syncthreads();

  // ======== x = weight @ v -> E region (e dead after scores) =============
  zero_acc(d2);
  mma_block<2, 64>(SC, S_LD, VT, S_LD, d2, lane, wm, wn);
  for_each<2>(d2, lane, wm, wn, [&](int r, int c, float v) {
    E[r * E_LD + c] = f2tf(v);
  });
  __syncthreads();  // X complete; SC (=W1) dead -> staging may resume

  // ======== h = lrelu([eq, x] @ W_f1^T), two accumulating passes =========
  zero_acc(d1);
  staged_mm<64, 4, 1>(EQ, E_LD, W_f1, W_f1, 64, 2 * kD, 0,
                      d1, W0, W1, tid, lane, wm, wn);
  staged_mm<64, 4, 1>(E, E_LD, W_f1, W_f1, 64, 2 * kD, kD,
                      d1, W0, W1, tid, lane, wm, wn);
  for_each<1>(d1, lane, wm, wn, [&](int r, int c, float v) {
    v = v > 0.f ? v : 0.01f * v;
    H[r * S_LD + c] = f2tf(v);  // H aliases T (dead)
  });

  // ======== Value = h @ W_f2^T -> gmem ===================================
  zero_acc(d1);
  staged_mm<64, 2, 1>(H, S_LD, W_f2, W_f2, 64, kN, 0,
                      d1, W0, W1, tid, lane, wm, wn);
  for_each<1>(d1, lane, wm, wn, [&](int r, int c, float v) {
    outV[((size_t)b * kN + r) * kFO + c] = v;
  });
}

}  // namespace

extern "C" void kernel_launch(void* const* d_in, const int* in_sizes, int n_in,
                              void* d_out, int out_size) {
  (void)in_sizes; (void)n_in; (void)out_size;
  const float* states    = (const float*)d_in[0];
  const float* actions   = (const float*)d_in[1];
  const float* W_embed   = (const float*)d_in[2];
  const float* b_embed   = (const float*)d_in[3];
  const float* W_k       = (const float*)d_in[4];
  const float* W_q       = (const float*)d_in[5];
  const float* W_v       = (const float*)d_in[6];
  const float* W_embed_q = (const float*)d_in[7];
  const float* b_embed_q = (const float*)d_in[8];
  const float* W_f1      = (const float*)d_in[9];
  const float* W_f2      = (const float*)d_in[10];

  float* outV = (float*)d_out;                 // Value [B,N,64]
  float* outW = outV + (size_t)kB * kN * kFO;  // weight [B,N,N]

  precompute_mt<<<kD, kD>>>(W_q, W_k);

  cudaFuncSetAttribute(critic_kernel,
                       cudaFuncAttributeMaxDynamicSharedMemorySize, SMEM_BYTES);
  critic_kernel<<<kB, kThreads, SMEM_BYTES>>>(states, actions, W_embed,
                                              b_embed, W_v, W_embed_q,
                                              b_embed_q, W_f1, W_f2,
                                              outV, outW);
}